// round 7
// baseline (speedup 1.0000x reference)
#include <cuda_runtime.h>
#include <cuda_bf16.h>
#include <math.h>
#include <stdint.h>

// Shapes (fixed): x[64,512,512] f32, k*[512,1024] f32, out[64,512,1024] f32
#define Bsz 64
#define Tsz 512
#define Dsz 512
#define Hsz 1024
#define Msz (Bsz * Tsz)   // 32768
#define KCB 1536          // B concat K: [whi | whi | wlo]
#define KCA 1024          // A concat K: [xhi | xlo]  (3rd term re-reads xhi)

// ---------------- device scratch (static, no runtime alloc) ----------------
__device__ float g_xz[(size_t)Msz * Hsz];
__device__ float g_xr[(size_t)Msz * Hsz];
__device__ float g_xh[(size_t)Msz * Hsz];
__device__ __align__(16) __nv_bfloat16 g_A[(size_t)Msz * KCA];       // 64 MB
__device__ __align__(16) __nv_bfloat16 g_B[3][(size_t)Hsz * KCB];    // 9 MB

// ---------------- PTX helpers (base-sm_103 features only) ----------------
__device__ __forceinline__ uint32_t smem_u32(const void* p) {
    uint32_t a;
    asm("{ .reg .u64 t; cvta.to.shared.u64 t, %1; cvt.u32.u64 %0, t; }" : "=r"(a) : "l"(p));
    return a;
}
__device__ __forceinline__ void cpasync16(uint32_t dst, const void* src) {
    asm volatile("cp.async.cg.shared.global [%0], [%1], 16;" :: "r"(dst), "l"(src) : "memory");
}
__device__ __forceinline__ void cp_commit() {
    asm volatile("cp.async.commit_group;" ::: "memory");
}
template <int N>
__device__ __forceinline__ void cp_wait() {
    asm volatile("cp.async.wait_group %0;" :: "n"(N) : "memory");
}
__device__ __forceinline__ void ldsm_x4(uint32_t& d0, uint32_t& d1, uint32_t& d2,
                                        uint32_t& d3, uint32_t addr) {
    asm volatile("ldmatrix.sync.aligned.m8n8.x4.shared.b16 {%0,%1,%2,%3}, [%4];"
                 : "=r"(d0), "=r"(d1), "=r"(d2), "=r"(d3) : "r"(addr));
}
__device__ __forceinline__ void mma16816(float& c0, float& c1, float& c2, float& c3,
                                         uint32_t a0, uint32_t a1, uint32_t a2, uint32_t a3,
                                         uint32_t b0, uint32_t b1) {
    asm volatile(
        "mma.sync.aligned.m16n8k16.row.col.f32.bf16.bf16.f32 "
        "{%0,%1,%2,%3}, {%4,%5,%6,%7}, {%8,%9}, {%0,%1,%2,%3};"
        : "+f"(c0), "+f"(c1), "+f"(c2), "+f"(c3)
        : "r"(a0), "r"(a1), "r"(a2), "r"(a3), "r"(b0), "r"(b1));
}

// ---------------- conversion kernels ----------------
// A: [m][0:512]=bf16hi(x), [512:1024]=bf16lo(x)
__global__ __launch_bounds__(256) void convA_kernel(const float* __restrict__ x) {
    int idx = blockIdx.x * blockDim.x + threadIdx.x;       // Msz*128 threads
    int m  = idx >> 7;
    int kg = (idx & 127) << 2;
    float4 v = *(const float4*)(x + (size_t)m * Dsz + kg);

    __nv_bfloat16 hi[4], lo[4];
    float vv[4] = {v.x, v.y, v.z, v.w};
#pragma unroll
    for (int j = 0; j < 4; j++) {
        hi[j] = __float2bfloat16(vv[j]);
        lo[j] = __float2bfloat16(vv[j] - __bfloat162float(hi[j]));
    }
    uint64_t hp, lp;
    memcpy(&hp, hi, 8);
    memcpy(&lp, lo, 8);
    __nv_bfloat16* row = g_A + (size_t)m * KCA + kg;
    *(uint64_t*)(row)       = hp;
    *(uint64_t*)(row + 512) = lp;
}

// B: [p][n][0:512]=bf16hi(W[:,n]), [512:1024]=hi, [1024:1536]=lo (transposed)
__global__ __launch_bounds__(256) void convB_kernel(const float* __restrict__ kz,
                                                    const float* __restrict__ kr,
                                                    const float* __restrict__ kh) {
    int idx = blockIdx.x * blockDim.x + threadIdx.x;       // 3*1024*64 threads
    int proj = idx >> 16;
    int r    = idx & 65535;
    int n  = r >> 6;
    int kg = (r & 63) << 3;
    const float* W = (proj == 0) ? kz : (proj == 1) ? kr : kh;

    __nv_bfloat16 hi[8], lo[8];
#pragma unroll
    for (int j = 0; j < 8; j++) {
        float w = W[(size_t)(kg + j) * Hsz + n];
        hi[j] = __float2bfloat16(w);
        lo[j] = __float2bfloat16(w - __bfloat162float(hi[j]));
    }
    uint4 hp, lp;
    memcpy(&hp, hi, 16);
    memcpy(&lp, lo, 16);
    __nv_bfloat16* row = g_B[proj] + (size_t)n * KCB + kg;
    *(uint4*)(row)        = hp;
    *(uint4*)(row + 512)  = hp;
    *(uint4*)(row + 1024) = lp;
}

// ---------------- mma.sync GEMM ----------------
// BM=128, BN=256, BK=64. 256 threads = 8 warps (2m x 4n), warp tile 64x64.
// 3-stage cp.async pipeline (48KB/stage), SW128-style swizzle, smem epilogue.
#define BKc 64
#define STAGES 3
#define NK (KCB / BKc)                  // 24
#define A_STG 16384                     // 128 rows * 128B
#define B_STG 32768                     // 256 rows * 128B
#define STG_BYTES (A_STG + B_STG)       // 49152
#define EPI_PITCH 260
#define SMEM_BYTES (STAGES * STG_BYTES) // 147456 (> epilogue 133120)

__global__ __launch_bounds__(256, 1) void gemm_kernel() {
    extern __shared__ char smem[];
    const uint32_t sb = smem_u32(smem);
    const int tid  = threadIdx.x;
    const int lane = tid & 31;
    const int wid  = tid >> 5;
    const int wm   = wid & 1;        // rows wm*64..+63
    const int wn   = wid >> 1;       // cols wn*64..+63

    const int proj = blockIdx.x >> 2;
    const int n0   = (blockIdx.x & 3) * 256;
    const int m0   = blockIdx.y * 128;
    const __nv_bfloat16* Ag = g_A + (size_t)m0 * KCA;
    const __nv_bfloat16* Bg = g_B[proj] + (size_t)n0 * KCB;
    float* Y = (proj == 0) ? g_xz : (proj == 1) ? g_xr : g_xh;

    float acc[4][8][4];
#pragma unroll
    for (int i = 0; i < 4; i++)
#pragma unroll
        for (int j = 0; j < 8; j++)
#pragma unroll
            for (int c = 0; c < 4; c++) acc[i][j][c] = 0.0f;

    // stage loader: 3072 x 16B chunks (A 1024, B 2048), 12 per thread.
    auto load_stage = [&](int stage, int kit) {
        const int a_k0 = (kit >= 16 ? kit - 16 : kit) * BKc;  // wrap 3rd term to hi
        const int b_k0 = kit * BKc;
        const uint32_t stg = sb + stage * STG_BYTES;
#pragma unroll
        for (int l = 0; l < 12; l++) {
            int cid = l * 256 + tid;
            if (cid < 1024) {
                int r = cid >> 3, c = cid & 7;
                cpasync16(stg + r * 128 + ((c ^ (r & 7)) << 4),
                          Ag + (size_t)r * KCA + a_k0 + c * 8);
            } else {
                int cid2 = cid - 1024;
                int r = cid2 >> 3, c = cid2 & 7;
                cpasync16(stg + A_STG + r * 128 + ((c ^ (r & 7)) << 4),
                          Bg + (size_t)r * KCB + b_k0 + c * 8);
            }
        }
        cp_commit();
    };

    load_stage(0, 0);
    load_stage(1, 1);

    const int frag_row = lane & 15;          // row within 16-row frag
    const int frag_hi  = lane >> 4;          // k-chunk selector

    for (int kit = 0; kit < NK; kit++) {
        const int stage = kit % STAGES;
        if (kit == NK - 1) cp_wait<0>(); else cp_wait<1>();
        __syncthreads();

        if (kit + 2 < NK) load_stage((kit + 2) % STAGES, kit + 2);

        const uint32_t abase = sb + stage * STG_BYTES;
        const uint32_t bbase = abase + A_STG;

#pragma unroll
        for (int kk = 0; kk < 4; kk++) {                 // 4 x K=16
            uint32_t a[4][4], b[8][2];
            const int c = kk * 2 + frag_hi;
#pragma unroll
            for (int i = 0; i < 4; i++) {
                int row = wm * 64 + i * 16 + frag_row;
                ldsm_x4(a[i][0], a[i][1], a[i][2], a[i][3],
                        abase + row * 128 + ((c ^ (row & 7)) << 4));
            }
#pragma unroll
            for (int j2 = 0; j2 < 4; j2++) {
                int row = wn * 64 + j2 * 16 + frag_row;
                // mats: {n0-7,k0-7},{n8-15,k0-7},{n0-7,k8-15},{n8-15,k8-15}
                ldsm_x4(b[j2 * 2][0], b[j2 * 2 + 1][0], b[j2 * 2][1], b[j2 * 2 + 1][1],
                        bbase + row * 128 + ((c ^ (row & 7)) << 4));
            }
#pragma unroll
            for (int i = 0; i < 4; i++)
#pragma unroll
                for (int j = 0; j < 8; j++)
                    mma16816(acc[i][j][0], acc[i][j][1], acc[i][j][2], acc[i][j][3],
                             a[i][0], a[i][1], a[i][2], a[i][3], b[j][0], b[j][1]);
        }
    }

    // ---- epilogue: fragments -> padded smem -> coalesced float4 stores ----
    __syncthreads();
    float* so = (float*)smem;
    const int qr = lane >> 2;
    const int qc = lane & 3;
#pragma unroll
    for (int i = 0; i < 4; i++) {
#pragma unroll
        for (int j = 0; j < 8; j++) {
            int r0 = wm * 64 + i * 16 + qr;
            int cc = wn * 64 + j * 8 + qc * 2;
            *(float2*)(so + r0 * EPI_PITCH + cc) =
                make_float2(acc[i][j][0], acc[i][j][1]);
            *(float2*)(so + (r0 + 8) * EPI_PITCH + cc) =
                make_float2(acc[i][j][2], acc[i][j][3]);
        }
    }
    __syncthreads();

#pragma unroll
    for (int l = 0; l < 32; l++) {
        int idx = l * 256 + tid;          // 8192 float4s (128 x 256)
        int row = idx >> 6;
        int c4  = (idx & 63) << 2;
        const float* s = so + row * EPI_PITCH + c4;
        float4 v = make_float4(s[0], s[1], s[2], s[3]);
        *(float4*)(Y + (size_t)(m0 + row) * Hsz + n0 + c4) = v;
    }
}

// ---------------- scan (diagonal recurrence), scalar, deep prefetch ----------------
__device__ __forceinline__ float fast_tanh(float a) {
    float e = __expf(2.0f * a);
    return 1.0f - __fdividef(2.0f, e + 1.0f);   // saturates correctly at +/-1
}

__global__ __launch_bounds__(256) void scan_kernel(
    const float* __restrict__ mz, const float* __restrict__ mr,
    const float* __restrict__ br, const float* __restrict__ bz,
    float* __restrict__ out)
{
    const int idx = blockIdx.x * blockDim.x + threadIdx.x;  // B*H threads
    const int b = idx >> 10;
    const int i = idx & (Hsz - 1);

    const float vmz = mz[i], vmr = mr[i], vbr = br[i], vbz = bz[i];

    const size_t base = (size_t)b * Tsz * Hsz + i;
    const float* gz = g_xz;
    const float* gr = g_xr;
    const float* gh = g_xh;

    const int PF = 8;                 // 24 independent loads in flight
    float az[PF], ar[PF], ah[PF];
#pragma unroll
    for (int p = 0; p < PF; p++) {
        size_t o = base + (size_t)p * Hsz;
        az[p] = __ldcs(gz + o);
        ar[p] = __ldcs(gr + o);
        ah[p] = __ldcs(gh + o);
    }

    float h = 0.0f;
    size_t off = base;
    for (int t0 = 0; t0 < Tsz; t0 += PF) {
#pragma unroll
        for (int p = 0; p < PF; p++) {
            const float pz = az[p], pr = ar[p], ph = ah[p];
            if (t0 + p + PF < Tsz) {
                size_t noff = off + (size_t)PF * Hsz;
                az[p] = __ldcs(gz + noff);
                ar[p] = __ldcs(gr + noff);
                ah[p] = __ldcs(gh + noff);
            }
            const float r    = fast_tanh(fmaf(h, vmr, pr) + vbr) + 1.0f;
            const float zarg = fmaf(h, vmz, pz) + vbz;
            const float z    = __fdividef(1.0f, 1.0f + __expf(-zarg));
            const float cand = fast_tanh(fmaf(r, h, ph));
            h = fmaf(z, h - cand, cand);
            __stcs(out + off, h);
            off += Hsz;
        }
    }
}

// ---------------- launch ----------------
extern "C" void kernel_launch(void* const* d_in, const int* in_sizes, int n_in,
                              void* d_out, int out_size)
{
    const float* x  = (const float*)d_in[0];
    const float* kz = (const float*)d_in[1];
    const float* kr = (const float*)d_in[2];
    const float* kh = (const float*)d_in[3];
    const float* mz = (const float*)d_in[4];
    const float* mr = (const float*)d_in[5];
    const float* br = (const float*)d_in[6];
    const float* bz = (const float*)d_in[7];
    float* out = (float*)d_out;

    cudaFuncSetAttribute(gemm_kernel, cudaFuncAttributeMaxDynamicSharedMemorySize,
                         SMEM_BYTES);

    convA_kernel<<<(Msz * 128) / 256, 256>>>(x);
    convB_kernel<<<(3 * Hsz * 64) / 256, 256>>>(kz, kr, kh);

    gemm_kernel<<<dim3(12, 256), 256, SMEM_BYTES>>>();

    scan_kernel<<<(Bsz * Hsz) / 256, 256>>>(mz, mr, br, bz, out);
}

// round 8
// speedup vs baseline: 2.1690x; 2.1690x over previous
#include <cuda_runtime.h>
#include <cuda_fp16.h>
#include <math.h>
#include <stdint.h>

// Shapes (fixed): x[64,512,512] f32, k*[512,1024] f32, out[64,512,1024] f32
#define Bsz 64
#define Tsz 512
#define Dsz 512
#define Hsz 1024
#define Msz (Bsz * Tsz)   // 32768
#define Kd  512           // plain fp16 GEMM K (no split; calibrated err ~5e-4)

// ---------------- device scratch (static, no runtime alloc) ----------------
__device__ float g_xz[(size_t)Msz * Hsz];
__device__ float g_xr[(size_t)Msz * Hsz];
__device__ float g_xh[(size_t)Msz * Hsz];
__device__ __align__(16) __half g_A[(size_t)Msz * Kd];        // 32 MB
__device__ __align__(16) __half g_B[3][(size_t)Hsz * Kd];     // 3 MB

// ---------------- PTX helpers (base-sm_103 features only) ----------------
__device__ __forceinline__ uint32_t smem_u32(const void* p) {
    uint32_t a;
    asm("{ .reg .u64 t; cvta.to.shared.u64 t, %1; cvt.u32.u64 %0, t; }" : "=r"(a) : "l"(p));
    return a;
}
__device__ __forceinline__ void cpasync16(uint32_t dst, const void* src) {
    asm volatile("cp.async.cg.shared.global [%0], [%1], 16;" :: "r"(dst), "l"(src) : "memory");
}
__device__ __forceinline__ void cp_commit() {
    asm volatile("cp.async.commit_group;" ::: "memory");
}
template <int N>
__device__ __forceinline__ void cp_wait() {
    asm volatile("cp.async.wait_group %0;" :: "n"(N) : "memory");
}
__device__ __forceinline__ void ldsm_x4(uint32_t& d0, uint32_t& d1, uint32_t& d2,
                                        uint32_t& d3, uint32_t addr) {
    asm volatile("ldmatrix.sync.aligned.m8n8.x4.shared.b16 {%0,%1,%2,%3}, [%4];"
                 : "=r"(d0), "=r"(d1), "=r"(d2), "=r"(d3) : "r"(addr));
}
__device__ __forceinline__ void ldsm_x2(uint32_t& d0, uint32_t& d1, uint32_t addr) {
    asm volatile("ldmatrix.sync.aligned.m8n8.x2.shared.b16 {%0,%1}, [%2];"
                 : "=r"(d0), "=r"(d1) : "r"(addr));
}
__device__ __forceinline__ void mma16816(float& c0, float& c1, float& c2, float& c3,
                                         uint32_t a0, uint32_t a1, uint32_t a2, uint32_t a3,
                                         uint32_t b0, uint32_t b1) {
    asm volatile(
        "mma.sync.aligned.m16n8k16.row.col.f32.f16.f16.f32 "
        "{%0,%1,%2,%3}, {%4,%5,%6,%7}, {%8,%9}, {%0,%1,%2,%3};"
        : "+f"(c0), "+f"(c1), "+f"(c2), "+f"(c3)
        : "r"(a0), "r"(a1), "r"(a2), "r"(a3), "r"(b0), "r"(b1));
}

// ---------------- conversion kernels ----------------
// A[m][k] = fp16(x[m][k])
__global__ __launch_bounds__(256) void convA_kernel(const float* __restrict__ x) {
    int idx = blockIdx.x * blockDim.x + threadIdx.x;       // Msz*128 threads
    int m  = idx >> 7;
    int kg = (idx & 127) << 2;
    float4 v = *(const float4*)(x + (size_t)m * Dsz + kg);
    __half h[4] = {__float2half(v.x), __float2half(v.y),
                   __float2half(v.z), __float2half(v.w)};
    uint64_t hp;
    memcpy(&hp, h, 8);
    *(uint64_t*)(g_A + (size_t)m * Kd + kg) = hp;
}

// B[p][n][k] = fp16(W[k][n])  (transposed, k-contiguous)
__global__ __launch_bounds__(256) void convB_kernel(const float* __restrict__ kz,
                                                    const float* __restrict__ kr,
                                                    const float* __restrict__ kh) {
    int idx = blockIdx.x * blockDim.x + threadIdx.x;       // 3*1024*64 threads
    int proj = idx >> 16;
    int r    = idx & 65535;
    int n  = r >> 6;
    int kg = (r & 63) << 3;
    const float* W = (proj == 0) ? kz : (proj == 1) ? kr : kh;

    __half h[8];
#pragma unroll
    for (int j = 0; j < 8; j++)
        h[j] = __float2half(W[(size_t)(kg + j) * Hsz + n]);
    uint4 hp;
    memcpy(&hp, h, 16);
    *(uint4*)(g_B[proj] + (size_t)n * Kd + kg) = hp;
}

// ---------------- mma.sync GEMM (R5 best-measured config, K=512) ----------------
// BM=256, BN=128, BK=64. 512 threads = 16 warps (4m x 4n), warp tile 64x32.
// 3-stage cp.async pipeline (48KB/stage), swizzled smem, smem epilogue.
#define BKc 64
#define STAGES 3
#define NK (Kd / BKc)                   // 8
#define A_STG 32768                     // 256 rows * 128B
#define B_STG 16384                     // 128 rows * 128B
#define STG_BYTES (A_STG + B_STG)       // 49152
#define EPI_PITCH 132
#define SMEM_BYTES (STAGES * STG_BYTES) // 147456 (> epilogue 67584)

__global__ __launch_bounds__(512, 1) void gemm_kernel() {
    extern __shared__ char smem[];
    const uint32_t sb = smem_u32(smem);
    const int tid  = threadIdx.x;
    const int lane = tid & 31;
    const int wid  = tid >> 5;
    const int wm   = wid & 3;        // rows wm*64..+63
    const int wn   = wid >> 2;       // cols wn*32..+31

    const int proj = blockIdx.x >> 3;
    const int n0   = (blockIdx.x & 7) * 128;
    const int m0   = blockIdx.y * 256;
    const __half* Ag = g_A + (size_t)m0 * Kd;
    const __half* Bg = g_B[proj] + (size_t)n0 * Kd;
    float* Y = (proj == 0) ? g_xz : (proj == 1) ? g_xr : g_xh;

    float acc[4][4][4];
#pragma unroll
    for (int i = 0; i < 4; i++)
#pragma unroll
        for (int j = 0; j < 4; j++)
#pragma unroll
            for (int c = 0; c < 4; c++) acc[i][j][c] = 0.0f;

    // stage loader: 3072 x 16B chunks (A 2048, B 1024), 6 per thread.
    auto load_stage = [&](int stage, int kit) {
        const int k0 = kit * BKc;
        const uint32_t stg = sb + stage * STG_BYTES;
#pragma unroll
        for (int l = 0; l < 6; l++) {
            int cid = l * 512 + tid;
            if (cid < 2048) {
                int r = cid >> 3, c = cid & 7;
                cpasync16(stg + r * 128 + ((c ^ (r & 7)) << 4),
                          Ag + (size_t)r * Kd + k0 + c * 8);
            } else {
                int cid2 = cid - 2048;
                int r = cid2 >> 3, c = cid2 & 7;
                cpasync16(stg + A_STG + r * 128 + ((c ^ (r & 7)) << 4),
                          Bg + (size_t)r * Kd + k0 + c * 8);
            }
        }
        cp_commit();
    };

    load_stage(0, 0);
    load_stage(1, 1);

    const int a_row_lane = lane & 15;
    const int a_chunk_hi = lane >> 4;
    const int b_row_lane = lane & 7;
    const int b_chunk_hi = (lane >> 3) & 1;

    for (int kit = 0; kit < NK; kit++) {
        const int stage = kit % STAGES;
        if (kit == NK - 1) cp_wait<0>(); else cp_wait<1>();
        __syncthreads();

        if (kit + 2 < NK) load_stage((kit + 2) % STAGES, kit + 2);

        const uint32_t abase = sb + stage * STG_BYTES;
        const uint32_t bbase = abase + A_STG;

#pragma unroll
        for (int kk = 0; kk < 4; kk++) {                 // 4 x K=16
            uint32_t a[4][4], b[4][2];
#pragma unroll
            for (int i = 0; i < 4; i++) {
                int row = wm * 64 + i * 16 + a_row_lane;
                int c = kk * 2 + a_chunk_hi;
                ldsm_x4(a[i][0], a[i][1], a[i][2], a[i][3],
                        abase + row * 128 + ((c ^ (row & 7)) << 4));
            }
#pragma unroll
            for (int j = 0; j < 4; j++) {
                int row = wn * 32 + j * 8 + b_row_lane;
                int c = kk * 2 + b_chunk_hi;
                ldsm_x2(b[j][0], b[j][1],
                        bbase + row * 128 + ((c ^ (row & 7)) << 4));
            }
#pragma unroll
            for (int i = 0; i < 4; i++)
#pragma unroll
                for (int j = 0; j < 4; j++)
                    mma16816(acc[i][j][0], acc[i][j][1], acc[i][j][2], acc[i][j][3],
                             a[i][0], a[i][1], a[i][2], a[i][3], b[j][0], b[j][1]);
        }
    }

    // ---- epilogue: fragments -> padded smem -> coalesced float4 stores ----
    __syncthreads();
    float* so = (float*)smem;
    const int qr = lane >> 2;
    const int qc = lane & 3;
#pragma unroll 1
    for (int half = 0; half < 2; half++) {       // m rows [half*128, +128)
        if ((wm >> 1) == half) {
            int lm = wm & 1;
#pragma unroll
            for (int i = 0; i < 4; i++) {
#pragma unroll
                for (int j = 0; j < 4; j++) {
                    int r0 = lm * 64 + i * 16 + qr;
                    int cc = wn * 32 + j * 8 + qc * 2;
                    *(float2*)(so + r0 * EPI_PITCH + cc) =
                        make_float2(acc[i][j][0], acc[i][j][1]);
                    *(float2*)(so + (r0 + 8) * EPI_PITCH + cc) =
                        make_float2(acc[i][j][2], acc[i][j][3]);
                }
            }
        }
        __syncthreads();
#pragma unroll
        for (int p = 0; p < 8; p++) {
            int row = p * 16 + (tid >> 5);
            int c4  = (tid & 31) << 2;
            const float* s = so + row * EPI_PITCH + c4;
            float4 v = make_float4(s[0], s[1], s[2], s[3]);
            *(float4*)(Y + (size_t)(m0 + half * 128 + row) * Hsz + n0 + c4) = v;
        }
        __syncthreads();
    }
}

// ---------------- scan (diagonal recurrence), scalar, PF=16 ----------------
__device__ __forceinline__ float fast_tanh(float a) {
    float e = __expf(2.0f * a);
    return 1.0f - __fdividef(2.0f, e + 1.0f);   // saturates correctly at +/-1
}

__global__ __launch_bounds__(256) void scan_kernel(
    const float* __restrict__ mz, const float* __restrict__ mr,
    const float* __restrict__ br, const float* __restrict__ bz,
    float* __restrict__ out)
{
    const int idx = blockIdx.x * blockDim.x + threadIdx.x;  // B*H threads
    const int b = idx >> 10;
    const int i = idx & (Hsz - 1);

    const float vmz = mz[i], vmr = mr[i], vbr = br[i], vbz = bz[i];

    const size_t base = (size_t)b * Tsz * Hsz + i;
    const float* gz = g_xz;
    const float* gr = g_xr;
    const float* gh = g_xh;

    const int PF = 16;                 // 48 independent loads in flight
    float az[PF], ar[PF], ah[PF];
#pragma unroll
    for (int p = 0; p < PF; p++) {
        size_t o = base + (size_t)p * Hsz;
        az[p] = __ldcs(gz + o);
        ar[p] = __ldcs(gr + o);
        ah[p] = __ldcs(gh + o);
    }

    float h = 0.0f;
    size_t off = base;
    for (int t0 = 0; t0 < Tsz; t0 += PF) {
#pragma unroll
        for (int p = 0; p < PF; p++) {
            const float pz = az[p], pr = ar[p], ph = ah[p];
            if (t0 + p + PF < Tsz) {
                size_t noff = off + (size_t)PF * Hsz;
                az[p] = __ldcs(gz + noff);
                ar[p] = __ldcs(gr + noff);
                ah[p] = __ldcs(gh + noff);
            }
            const float r    = fast_tanh(fmaf(h, vmr, pr) + vbr) + 1.0f;
            const float zarg = fmaf(h, vmz, pz) + vbz;
            const float z    = __fdividef(1.0f, 1.0f + __expf(-zarg));
            const float cand = fast_tanh(fmaf(r, h, ph));
            h = fmaf(z, h - cand, cand);
            __stcs(out + off, h);
            off += Hsz;
        }
    }
}

// ---------------- launch ----------------
extern "C" void kernel_launch(void* const* d_in, const int* in_sizes, int n_in,
                              void* d_out, int out_size)
{
    const float* x  = (const float*)d_in[0];
    const float* kz = (const float*)d_in[1];
    const float* kr = (const float*)d_in[2];
    const float* kh = (const float*)d_in[3];
    const float* mz = (const float*)d_in[4];
    const float* mr = (const float*)d_in[5];
    const float* br = (const float*)d_in[6];
    const float* bz = (const float*)d_in[7];
    float* out = (float*)d_out;

    cudaFuncSetAttribute(gemm_kernel, cudaFuncAttributeMaxDynamicSharedMemorySize,
                         SMEM_BYTES);

    convA_kernel<<<(Msz * 128) / 256, 256>>>(x);
    convB_kernel<<<(3 * Hsz * 64) / 256, 256>>>(kz, kr, kh);

    gemm_kernel<<<dim3(24, 128), 512, SMEM_BYTES>>>();

    scan_kernel<<<(Bsz * Hsz) / 256, 256>>>(mz, mr, br, bz, out);
}

// round 10
// speedup vs baseline: 2.6371x; 1.2158x over previous
#include <cuda_runtime.h>
#include <cuda_fp16.h>
#include <math.h>
#include <stdint.h>

// Shapes (fixed): x[64,512,512] f32, k*[512,1024] f32, out[64,512,1024] f32
#define Bsz 64
#define Tsz 512
#define Dsz 512
#define Hsz 1024
#define Msz (Bsz * Tsz)   // 32768
#define Kd  512
#define Nc  3072          // fused N = 3*H, columns interleaved per channel pair

// ---------------- device scratch (static, no runtime alloc) ----------------
// g_P[m][col]: col = (n>>1)*6 + (n&1)*3 + p  -> row layout [z0 r0 h0 z1 r1 h1 | ...]
__device__ __align__(16) __half g_P[(size_t)Msz * Nc];        // 192 MB
__device__ __align__(16) __half g_A[(size_t)Msz * Kd];        // 32 MB
__device__ __align__(16) __half g_B[(size_t)Nc * Kd];         // 3 MB

// ---------------- PTX helpers (base-sm_103 features only) ----------------
__device__ __forceinline__ uint32_t smem_u32(const void* p) {
    uint32_t a;
    asm("{ .reg .u64 t; cvta.to.shared.u64 t, %1; cvt.u32.u64 %0, t; }" : "=r"(a) : "l"(p));
    return a;
}
__device__ __forceinline__ void cpasync16(uint32_t dst, const void* src) {
    asm volatile("cp.async.cg.shared.global [%0], [%1], 16;" :: "r"(dst), "l"(src) : "memory");
}
__device__ __forceinline__ void cp_commit() {
    asm volatile("cp.async.commit_group;" ::: "memory");
}
template <int N>
__device__ __forceinline__ void cp_wait() {
    asm volatile("cp.async.wait_group %0;" :: "n"(N) : "memory");
}
__device__ __forceinline__ void ldsm_x4(uint32_t& d0, uint32_t& d1, uint32_t& d2,
                                        uint32_t& d3, uint32_t addr) {
    asm volatile("ldmatrix.sync.aligned.m8n8.x4.shared.b16 {%0,%1,%2,%3}, [%4];"
                 : "=r"(d0), "=r"(d1), "=r"(d2), "=r"(d3) : "r"(addr));
}
__device__ __forceinline__ void ldsm_x2(uint32_t& d0, uint32_t& d1, uint32_t addr) {
    asm volatile("ldmatrix.sync.aligned.m8n8.x2.shared.b16 {%0,%1}, [%2];"
                 : "=r"(d0), "=r"(d1) : "r"(addr));
}
__device__ __forceinline__ void mma16816(float& c0, float& c1, float& c2, float& c3,
                                         uint32_t a0, uint32_t a1, uint32_t a2, uint32_t a3,
                                         uint32_t b0, uint32_t b1) {
    asm volatile(
        "mma.sync.aligned.m16n8k16.row.col.f32.f16.f16.f32 "
        "{%0,%1,%2,%3}, {%4,%5,%6,%7}, {%8,%9}, {%0,%1,%2,%3};"
        : "+f"(c0), "+f"(c1), "+f"(c2), "+f"(c3)
        : "r"(a0), "r"(a1), "r"(a2), "r"(a3), "r"(b0), "r"(b1));
}

// ---------------- conversion kernels ----------------
// A[m][k] = fp16(x[m][k])
__global__ __launch_bounds__(256) void convA_kernel(const float* __restrict__ x) {
    int idx = blockIdx.x * blockDim.x + threadIdx.x;       // Msz*128 threads
    int m  = idx >> 7;
    int kg = (idx & 127) << 2;
    float4 v = *(const float4*)(x + (size_t)m * Dsz + kg);
    __half h[4] = {__float2half(v.x), __float2half(v.y),
                   __float2half(v.z), __float2half(v.w)};
    uint64_t hp;
    memcpy(&hp, h, 8);
    *(uint64_t*)(g_A + (size_t)m * Kd + kg) = hp;
}

// B[col][k] = fp16(W_p[k][n]) with col = (n>>1)*6 + (n&1)*3 + p
__global__ __launch_bounds__(256) void convB_kernel(const float* __restrict__ kz,
                                                    const float* __restrict__ kr,
                                                    const float* __restrict__ kh) {
    int idx = blockIdx.x * blockDim.x + threadIdx.x;       // 3*1024*64 threads
    int proj = idx >> 16;
    int r    = idx & 65535;
    int n  = r >> 6;
    int kg = (r & 63) << 3;
    const float* W = (proj == 0) ? kz : (proj == 1) ? kr : kh;
    const int col = (n >> 1) * 6 + (n & 1) * 3 + proj;

    __half h[8];
#pragma unroll
    for (int j = 0; j < 8; j++)
        h[j] = __float2half(W[(size_t)(kg + j) * Hsz + n]);
    uint4 hp;
    memcpy(&hp, h, 16);
    *(uint4*)(g_B + (size_t)col * Kd + kg) = hp;
}

// ---------------- fused mma.sync GEMM (M=32768, N=3072, K=512) ----------------
// BM=128, BN=128, BK=64. 256 threads = 8 warps (2m x 4n), warp tile 64x32.
// 3-stage cp.async pipeline (32KB/stage = 96KB), 2 CTAs/SM, fp16 epilogue.
#define BKc 64
#define STAGES 3
#define NK (Kd / BKc)                   // 8
#define A_STG 16384                     // 128 rows * 128B
#define B_STG 16384
#define STG_BYTES (A_STG + B_STG)       // 32768
#define SMEM_BYTES (STAGES * STG_BYTES) // 98304
#define EPI_PITCH_B 272                 // bytes per row in epilogue staging

__global__ __launch_bounds__(256, 2) void gemm_kernel() {
    extern __shared__ char smem[];
    const uint32_t sb = smem_u32(smem);
    const int tid  = threadIdx.x;
    const int lane = tid & 31;
    const int wid  = tid >> 5;
    const int wm   = wid & 1;        // rows wm*64..+63
    const int wn   = wid >> 1;       // cols wn*32..+31

    const int n0 = blockIdx.x * 128;
    const int m0 = blockIdx.y * 128;
    const __half* Ag = g_A + (size_t)m0 * Kd;
    const __half* Bg = g_B + (size_t)n0 * Kd;

    float acc[4][4][4];
#pragma unroll
    for (int i = 0; i < 4; i++)
#pragma unroll
        for (int j = 0; j < 4; j++)
#pragma unroll
            for (int c = 0; c < 4; c++) acc[i][j][c] = 0.0f;

    // stage loader: 2048 x 16B chunks (A 1024, B 1024), 8 per thread.
    auto load_stage = [&](int stage, int kit) {
        const int k0 = kit * BKc;
        const uint32_t stg = sb + stage * STG_BYTES;
#pragma unroll
        for (int l = 0; l < 8; l++) {
            int cid = l * 256 + tid;
            int isB = cid >> 10;
            int r   = (cid >> 3) & 127;
            int c   = cid & 7;
            const __half* src = (isB ? Bg : Ag) + (size_t)r * Kd + k0 + c * 8;
            cpasync16(stg + isB * A_STG + r * 128 + ((c ^ (r & 7)) << 4), src);
        }
        cp_commit();
    };

    load_stage(0, 0);
    load_stage(1, 1);

    const int a_row_lane = lane & 15;
    const int a_chunk_hi = lane >> 4;
    const int b_row_lane = lane & 7;
    const int b_chunk_hi = (lane >> 3) & 1;

    for (int kit = 0; kit < NK; kit++) {
        const int stage = kit % STAGES;
        if (kit == NK - 1) cp_wait<0>(); else cp_wait<1>();
        __syncthreads();

        if (kit + 2 < NK) load_stage((kit + 2) % STAGES, kit + 2);

        const uint32_t abase = sb + stage * STG_BYTES;
        const uint32_t bbase = abase + A_STG;

#pragma unroll
        for (int kk = 0; kk < 4; kk++) {                 // 4 x K=16
            uint32_t a[4][4], b[4][2];
#pragma unroll
            for (int i = 0; i < 4; i++) {
                int row = wm * 64 + i * 16 + a_row_lane;
                int c = kk * 2 + a_chunk_hi;
                ldsm_x4(a[i][0], a[i][1], a[i][2], a[i][3],
                        abase + row * 128 + ((c ^ (row & 7)) << 4));
            }
#pragma unroll
            for (int j = 0; j < 4; j++) {
                int row = wn * 32 + j * 8 + b_row_lane;
                int c = kk * 2 + b_chunk_hi;
                ldsm_x2(b[j][0], b[j][1],
                        bbase + row * 128 + ((c ^ (row & 7)) << 4));
            }
#pragma unroll
            for (int i = 0; i < 4; i++)
#pragma unroll
                for (int j = 0; j < 4; j++)
                    mma16816(acc[i][j][0], acc[i][j][1], acc[i][j][2], acc[i][j][3],
                             a[i][0], a[i][1], a[i][2], a[i][3], b[j][0], b[j][1]);
        }
    }

    // ---- epilogue: f32 frags -> half2 smem staging -> coalesced 16B stores ----
    __syncthreads();
    const int qr = lane >> 2;
    const int qc = lane & 3;
#pragma unroll
    for (int i = 0; i < 4; i++) {
#pragma unroll
        for (int j = 0; j < 4; j++) {
            int r0 = wm * 64 + i * 16 + qr;
            int cb = (wn * 32 + j * 8 + qc * 2) * 2;   // byte col within row
            __half2 h2a = __floats2half2_rn(acc[i][j][0], acc[i][j][1]);
            __half2 h2b = __floats2half2_rn(acc[i][j][2], acc[i][j][3]);
            *(__half2*)(smem + r0 * EPI_PITCH_B + cb)       = h2a;
            *(__half2*)(smem + (r0 + 8) * EPI_PITCH_B + cb) = h2b;
        }
    }
    __syncthreads();

#pragma unroll
    for (int l = 0; l < 8; l++) {
        int idx = l * 256 + tid;          // 2048 uint4 (128 rows x 256B)
        int row = idx >> 4;
        int c16 = idx & 15;
        uint4 v = *(uint4*)(smem + row * EPI_PITCH_B + c16 * 16);
        *(uint4*)(g_P + (size_t)(m0 + row) * Nc + n0 + c16 * 8) = v;
    }
}

// ---------------- scan: 2 packed channels per thread ----------------
__device__ __forceinline__ float fast_tanh(float a) {
    float e = __expf(2.0f * a);
    return 1.0f - __fdividef(2.0f, e + 1.0f);   // saturates correctly at +/-1
}
__device__ __forceinline__ float sigm(float a) {
    return __fdividef(1.0f, 1.0f + __expf(-a));
}

__global__ __launch_bounds__(128) void scan_kernel(
    const float* __restrict__ mz, const float* __restrict__ mr,
    const float* __restrict__ br, const float* __restrict__ bz,
    float* __restrict__ out)
{
    const int idx = blockIdx.x * blockDim.x + threadIdx.x;  // B*H/2 = 32768
    const int b  = idx >> 9;          // batch
    const int jj = idx & 511;         // channel pair
    const int i0 = jj * 2;

    const float vmz0 = mz[i0], vmz1 = mz[i0 + 1];
    const float vmr0 = mr[i0], vmr1 = mr[i0 + 1];
    const float vbr0 = br[i0], vbr1 = br[i0 + 1];
    const float vbz0 = bz[i0], vbz1 = bz[i0 + 1];

    // packed projections: 3 uints = 12B = [z0 r0][h0 z1][r1 h1] per t
    const uint32_t* src = (const uint32_t*)(g_P + (size_t)b * Tsz * Nc + jj * 6);
    const int STRIDE_U = Nc / 2;      // uints per timestep (1536)

    const int PF = 8;
    uint32_t u0[PF], u1[PF], u2[PF];
#pragma unroll
    for (int p = 0; p < PF; p++) {
        const uint32_t* s = src + (size_t)p * STRIDE_U;
        u0[p] = __ldcs(s); u1[p] = __ldcs(s + 1); u2[p] = __ldcs(s + 2);
    }

    float h0 = 0.0f, h1 = 0.0f;
    float* op = out + (size_t)b * Tsz * Hsz + i0;
    const uint32_t* sp = src;

    for (int t0 = 0; t0 < Tsz; t0 += PF) {
#pragma unroll
        for (int p = 0; p < PF; p++) {
            float2 a0 = __half22float2(*(__half2*)&u0[p]);  // z0 r0
            float2 a1 = __half22float2(*(__half2*)&u1[p]);  // h0 z1
            float2 a2 = __half22float2(*(__half2*)&u2[p]);  // r1 h1
            if (t0 + p + PF < Tsz) {
                const uint32_t* s = sp + (size_t)(p + PF) * STRIDE_U;
                u0[p] = __ldcs(s); u1[p] = __ldcs(s + 1); u2[p] = __ldcs(s + 2);
            }
            // channel 0
            {
                const float r    = fast_tanh(fmaf(h0, vmr0, a0.y) + vbr0) + 1.0f;
                const float z    = sigm(fmaf(h0, vmz0, a0.x) + vbz0);
                const float cand = fast_tanh(fmaf(r, h0, a1.x));
                h0 = fmaf(z, h0 - cand, cand);
            }
            // channel 1
            {
                const float r    = fast_tanh(fmaf(h1, vmr1, a2.x) + vbr1) + 1.0f;
                const float z    = sigm(fmaf(h1, vmz1, a1.y) + vbz1);
                const float cand = fast_tanh(fmaf(r, h1, a2.y));
                h1 = fmaf(z, h1 - cand, cand);
            }
            __stcs((float2*)op, make_float2(h0, h1));
            op += Hsz;
        }
        sp += (size_t)PF * STRIDE_U;
    }
}

// ---------------- launch ----------------
extern "C" void kernel_launch(void* const* d_in, const int* in_sizes, int n_in,
                              void* d_out, int out_size)
{
    const float* x  = (const float*)d_in[0];
    const float* kz = (const float*)d_in[1];
    const float* kr = (const float*)d_in[2];
    const float* kh = (const float*)d_in[3];
    const float* mz = (const float*)d_in[4];
    const float* mr = (const float*)d_in[5];
    const float* br = (const float*)d_in[6];
    const float* bz = (const float*)d_in[7];
    float* out = (float*)d_out;

    cudaFuncSetAttribute(gemm_kernel, cudaFuncAttributeMaxDynamicSharedMemorySize,
                         SMEM_BYTES);

    convA_kernel<<<(Msz * 128) / 256, 256>>>(x);
    convB_kernel<<<(3 * Hsz * 64) / 256, 256>>>(kz, kr, kh);

    gemm_kernel<<<dim3(Nc / 128, Msz / 128), 256, SMEM_BYTES>>>();

    scan_kernel<<<(Bsz * Hsz / 2) / 128, 128>>>(mz, mr, br, bz, out);
}